// round 1
// baseline (speedup 1.0000x reference)
#include <cuda_runtime.h>

// ---------------------------------------------------------------------------
// WT_series_decomp: 4-level lowpass DWT analysis + synthesis, season = x - trend
// One CTA per (b,c) row. Whole pipeline fused in shared memory.
//
// Analysis (stride-2 conv, pad 6, correlation with H = reverse(DEC_LO)):
//   out[o] = sum_k in[2o-6+k] * H[k],  guard-free via zeroed margins.
// Synthesis (transposed conv, lhs_dilation 2, pad 1, correlation with G=DEC_LO):
//   o even: out[o] = sum_j lo[o/2+j]     * G[2j+1]
//   o odd : out[o] = sum_j lo[(o-1)/2+j] * G[2j]
//   (index range always within [0,n) -> no guards; trims are automatic)
// ---------------------------------------------------------------------------

#define NT      512
#define N0      32768
#define NROWS   512
#define HALF    16777216   // 512 * 32768, offset of trend in d_out

// Buffer geometry (floats), each with 8-float zeroed front margin
#define X_ALLOC   (8 + 32768 + 8)          // 32784
#define B1_ALLOC  (8 + 16388 + 8)          // 16404
#define B2_ALLOC  (8 + 8198 + 10)          // 8216
#define SMEM_FLOATS (X_ALLOC + B1_ALLOC + B2_ALLOC)
#define SMEM_BYTES  (SMEM_FLOATS * 4)      // 229616 <= 232448 (227 KB opt-in)

// DEC_LO
#define G0 (-0.010597401784997278f)
#define G1 ( 0.032883011666982945f)
#define G2 ( 0.030841381835986965f)
#define G3 (-0.18703481171888114f)
#define G4 (-0.02798376941698385f)
#define G5 ( 0.6308807679295904f)
#define G6 ( 0.7148465705525415f)
#define G7 ( 0.23037781330885523f)
// H[k] = DEC_LO[7-k]
#define H0 G7
#define H1 G6
#define H2 G5
#define H3 G4
#define H4 G3
#define H5 G2
#define H6 G1
#define H7 G0

// Analysis filter bank: out[o] = sum_k in[2o-6+k]*H[k], o in [0, n_out).
// Also zero-fills 8 floats past the end so the next analysis stage is guard-free.
__device__ __forceinline__ void afb(const float* __restrict__ in,
                                    float* __restrict__ out,
                                    int n_out, int tid) {
    for (int o = tid; o < n_out; o += NT) {
        const float2* p = (const float2*)(in + 2 * o - 6);  // 2o-6 even -> aligned
        float2 a = p[0], b = p[1], c = p[2], d = p[3];
        float s = a.x * H0;
        s = fmaf(a.y, H1, s);
        s = fmaf(b.x, H2, s);
        s = fmaf(b.y, H3, s);
        s = fmaf(c.x, H4, s);
        s = fmaf(c.y, H5, s);
        s = fmaf(d.x, H6, s);
        s = fmaf(d.y, H7, s);
        out[o] = s;
    }
    if (tid < 8) out[n_out + tid] = 0.0f;
}

// Synthesis filter bank (transposed conv). No guards needed.
__device__ __forceinline__ void sfb(const float* __restrict__ in,
                                    float* __restrict__ out,
                                    int n_out, int tid) {
    for (int o = tid; o < n_out; o += NT) {
        int j = o >> 1;
        bool odd = (o & 1) != 0;
        float t0 = odd ? G0 : G1;
        float t1 = odd ? G2 : G3;
        float t2 = odd ? G4 : G5;
        float t3 = odd ? G6 : G7;
        float s = in[j] * t0;
        s = fmaf(in[j + 1], t1, s);
        s = fmaf(in[j + 2], t2, s);
        s = fmaf(in[j + 3], t3, s);
        out[o] = s;
    }
}

__global__ void __launch_bounds__(NT, 1)
wt_kernel(const float* __restrict__ x, float* __restrict__ out) {
    extern __shared__ float sm[];
    float* X  = sm + 8;
    float* B1 = sm + X_ALLOC + 8;
    float* B2 = sm + X_ALLOC + B1_ALLOC + 8;

    const int tid = threadIdx.x;
    const int row = blockIdx.x;
    const float* xr = x + (size_t)row * N0;

    // Zero front margins + X right margin
    if (tid < 8) {
        X[tid - 8]  = 0.0f;
        B1[tid - 8] = 0.0f;
        B2[tid - 8] = 0.0f;
        X[N0 + tid] = 0.0f;
    }

    // Load x row into smem (float4, coalesced). X starts at 32B-aligned offset.
    {
        const float4* x4 = (const float4*)xr;
        float4* X4 = (float4*)X;
#pragma unroll
        for (int i = 0; i < 16; ++i) {
            int idx = tid + i * NT;
            X4[idx] = x4[idx];
        }
    }
    __syncthreads();

    // Analysis: 32768 -> 16387 -> 8197 -> 4102 -> 2054
    afb(X,  B1, 16387, tid); __syncthreads();
    afb(B1, B2, 8197,  tid); __syncthreads();
    afb(B2, B1, 4102,  tid); __syncthreads();
    afb(B1, B2, 2054,  tid); __syncthreads();

    // Synthesis: 2054 -> 4102 -> 8198 -> 16388 (trims are implicit)
    sfb(B2, B1, 4102,  tid); __syncthreads();
    sfb(B1, B2, 8198,  tid); __syncthreads();
    sfb(B2, B1, 16388, tid); __syncthreads();

    // Final upsample 16387 -> 32768 fused with season = x - trend, streamed out.
    float* season = out + (size_t)row * N0;
    float* trend  = out + (size_t)HALF + (size_t)row * N0;
    const float* t3 = B1;
    const float4* X4 = (const float4*)X;
    float4* s4p = (float4*)season;
    float4* t4p = (float4*)trend;

#pragma unroll
    for (int i = 0; i < 16; ++i) {
        int idx = tid + i * NT;          // float4 output index, 0..8191
        int j = idx * 2;                 // t3 base index (even -> float2 aligned)
        float2 u = *(const float2*)(t3 + j);
        float2 v = *(const float2*)(t3 + j + 2);
        float  w = t3[j + 4];

        float4 t;
        // o = 4*idx   (even): lo[2i..2i+3] . {G1,G3,G5,G7}
        t.x = fmaf(u.x, G1, fmaf(u.y, G3, fmaf(v.x, G5, v.y * G7)));
        // o = 4*idx+1 (odd) : lo[2i..2i+3] . {G0,G2,G4,G6}
        t.y = fmaf(u.x, G0, fmaf(u.y, G2, fmaf(v.x, G4, v.y * G6)));
        // o = 4*idx+2 (even): lo[2i+1..2i+4] . {G1,G3,G5,G7}
        t.z = fmaf(u.y, G1, fmaf(v.x, G3, fmaf(v.y, G5, w * G7)));
        // o = 4*idx+3 (odd) : lo[2i+1..2i+4] . {G0,G2,G4,G6}
        t.w = fmaf(u.y, G0, fmaf(v.x, G2, fmaf(v.y, G4, w * G6)));

        float4 xv = X4[idx];
        float4 se = make_float4(xv.x - t.x, xv.y - t.y, xv.z - t.z, xv.w - t.w);
        s4p[idx] = se;
        t4p[idx] = t;
    }
}

extern "C" void kernel_launch(void* const* d_in, const int* in_sizes, int n_in,
                              void* d_out, int out_size) {
    const float* x = (const float*)d_in[0];
    float* out = (float*)d_out;
    cudaFuncSetAttribute(wt_kernel, cudaFuncAttributeMaxDynamicSharedMemorySize,
                         SMEM_BYTES);
    wt_kernel<<<NROWS, NT, SMEM_BYTES>>>(x, out);
}

// round 3
// speedup vs baseline: 1.1213x; 1.1213x over previous
#include <cuda_runtime.h>

// ---------------------------------------------------------------------------
// WT_series_decomp: 4-level lowpass DWT analysis + synthesis, season = x - trend
// One CTA (1024 threads) per (b,c) row. Whole pipeline fused in shared memory.
//
// Analysis:  out[o] = sum_k in[2o-6+k] * H[k]   (H = reverse(DEC_LO), pad 6)
// Synthesis: o even: out[o] = sum_j in[o/2+j]*G[2j+1]
//            o odd : out[o] = sum_j in[(o-1)/2+j]*G[2j]
// ---------------------------------------------------------------------------

#define NT      1024
#define N0      32768
#define NROWS   512
#define HALF    16777216   // 512 * 32768, offset of trend in d_out

// Buffer geometry (floats), each with 8-float zeroed front margin
#define X_ALLOC   (8 + 32768 + 8)          // 32784
#define B1_ALLOC  (8 + 16388 + 8)          // 16404
#define B2_ALLOC  (8 + 8198 + 10)          // 8216
#define SMEM_FLOATS (X_ALLOC + B1_ALLOC + B2_ALLOC)
#define SMEM_BYTES  (SMEM_FLOATS * 4)      // 229616 bytes

// DEC_LO
#define G0 (-0.010597401784997278f)
#define G1 ( 0.032883011666982945f)
#define G2 ( 0.030841381835986965f)
#define G3 (-0.18703481171888114f)
#define G4 (-0.02798376941698385f)
#define G5 ( 0.6308807679295904f)
#define G6 ( 0.7148465705525415f)
#define G7 ( 0.23037781330885523f)
// H[k] = DEC_LO[7-k]
#define H0 G7
#define H1 G6
#define H2 G5
#define H3 G4
#define H4 G3
#define H5 G2
#define H6 G1
#define H7 G0

// 8-tap dot with H over 8 consecutive floats given as 4 float2
__device__ __forceinline__ float dot8(float2 a, float2 b, float2 c, float2 d) {
    float s = a.x * H0;
    s = fmaf(a.y, H1, s);
    s = fmaf(b.x, H2, s);
    s = fmaf(b.y, H3, s);
    s = fmaf(c.x, H4, s);
    s = fmaf(c.y, H5, s);
    s = fmaf(d.x, H6, s);
    s = fmaf(d.y, H7, s);
    return s;
}

// Analysis: pairwise (outputs 2m, 2m+1 share 5 float2 loads).
// Zero-fills 8 floats past the end for the next guard-free stage.
__device__ __forceinline__ void afb(const float* __restrict__ in,
                                    float* __restrict__ out,
                                    int n_out, int tid) {
    const int npair = (n_out + 1) >> 1;
    for (int m = tid; m < npair; m += NT) {
        const float2* p = (const float2*)(in + 4 * m - 6);  // even index -> aligned
        float2 a = p[0], b = p[1], c = p[2], d = p[3], e = p[4];
        float s0 = dot8(a, b, c, d);  // o = 2m
        float s1 = dot8(b, c, d, e);  // o = 2m+1
        int o = 2 * m;
        if (o + 1 < n_out) {
            *(float2*)(out + o) = make_float2(s0, s1);
        } else {
            out[o] = s0;  // odd n_out tail
        }
    }
    if (tid < 8) out[n_out + tid] = 0.0f;
}

// Synthesis: quad (outputs 4q..4q+3 share 3 float2 loads).
// Tail (n_out % 4 == 2) stores only the first two lanes.
__device__ __forceinline__ void sfb(const float* __restrict__ in,
                                    float* __restrict__ out,
                                    int n_out, int tid) {
    const int nq = (n_out + 3) >> 2;
    for (int q = tid; q < nq; q += NT) {
        const float2* p = (const float2*)(in + 2 * q);
        float2 u = p[0], v = p[1], w = p[2];
        float4 t;
        t.x = fmaf(u.x, G1, fmaf(u.y, G3, fmaf(v.x, G5, v.y * G7)));  // o=4q   even
        t.y = fmaf(u.x, G0, fmaf(u.y, G2, fmaf(v.x, G4, v.y * G6)));  // o=4q+1 odd
        t.z = fmaf(u.y, G1, fmaf(v.x, G3, fmaf(v.y, G5, w.x * G7)));  // o=4q+2 even
        t.w = fmaf(u.y, G0, fmaf(v.x, G2, fmaf(v.y, G4, w.x * G6)));  // o=4q+3 odd
        int o = 4 * q;
        if (o + 3 < n_out) {
            *(float4*)(out + o) = t;
        } else {
            *(float2*)(out + o) = make_float2(t.x, t.y);  // n_out%4==2 tail
        }
    }
}

__global__ void __launch_bounds__(NT, 1)
wt_kernel(const float* __restrict__ x, float* __restrict__ out) {
    extern __shared__ float sm[];
    float* X  = sm + 8;
    float* B1 = sm + X_ALLOC + 8;
    float* B2 = sm + X_ALLOC + B1_ALLOC + 8;

    const int tid = threadIdx.x;
    const int row = blockIdx.x;
    const float* xr = x + (size_t)row * N0;

    // Zero front margins + X right margin
    if (tid < 8) {
        X[tid - 8]  = 0.0f;
        B1[tid - 8] = 0.0f;
        B2[tid - 8] = 0.0f;
        X[N0 + tid] = 0.0f;
    }

    // Load x row into smem (float4, coalesced)
    {
        const float4* x4 = (const float4*)xr;
        float4* X4 = (float4*)X;
#pragma unroll 4
        for (int i = 0; i < 8; ++i) {
            int idx = tid + i * NT;
            X4[idx] = x4[idx];
        }
    }
    __syncthreads();

    // Analysis: 32768 -> 16387 -> 8197 -> 4102 -> 2054
    afb(X,  B1, 16387, tid); __syncthreads();
    afb(B1, B2, 8197,  tid); __syncthreads();
    afb(B2, B1, 4102,  tid); __syncthreads();
    afb(B1, B2, 2054,  tid); __syncthreads();

    // Synthesis: 2054 -> 4102 -> 8198 -> 16388 (trims are implicit)
    sfb(B2, B1, 4102,  tid); __syncthreads();
    sfb(B1, B2, 8198,  tid); __syncthreads();
    sfb(B2, B1, 16388, tid); __syncthreads();

    // Final upsample 16387 -> 32768 fused with season = x - trend, streamed out.
    float* season = out + (size_t)row * N0;
    float* trend  = out + (size_t)HALF + (size_t)row * N0;
    const float* t3 = B1;
    const float4* X4 = (const float4*)X;
    float4* s4p = (float4*)season;
    float4* t4p = (float4*)trend;

#pragma unroll 2
    for (int i = 0; i < 8; ++i) {
        int idx = tid + i * NT;          // float4 output index, 0..8191
        int j = idx * 2;                 // t3 base index (even -> float2 aligned)
        float2 u = *(const float2*)(t3 + j);
        float2 v = *(const float2*)(t3 + j + 2);
        float  w = t3[j + 4];

        float4 t;
        t.x = fmaf(u.x, G1, fmaf(u.y, G3, fmaf(v.x, G5, v.y * G7)));
        t.y = fmaf(u.x, G0, fmaf(u.y, G2, fmaf(v.x, G4, v.y * G6)));
        t.z = fmaf(u.y, G1, fmaf(v.x, G3, fmaf(v.y, G5, w * G7)));
        t.w = fmaf(u.y, G0, fmaf(v.x, G2, fmaf(v.y, G4, w * G6)));

        float4 xv = X4[idx];
        float4 se = make_float4(xv.x - t.x, xv.y - t.y, xv.z - t.z, xv.w - t.w);
        s4p[idx] = se;
        t4p[idx] = t;
    }
}

extern "C" void kernel_launch(void* const* d_in, const int* in_sizes, int n_in,
                              void* d_out, int out_size) {
    const float* x = (const float*)d_in[0];
    float* out = (float*)d_out;
    cudaFuncSetAttribute(wt_kernel, cudaFuncAttributeMaxDynamicSharedMemorySize,
                         SMEM_BYTES);
    wt_kernel<<<NROWS, NT, SMEM_BYTES>>>(x, out);
}

// round 5
// speedup vs baseline: 1.3201x; 1.1774x over previous
#include <cuda_runtime.h>

// ---------------------------------------------------------------------------
// WT_series_decomp: 4-level lowpass DWT analysis + synthesis, season = x - trend
// One CTA (1024 threads) per row; 2 CTAs resident per SM (smem = 98.5KB).
// x is streamed from global in stage 1 and the final subtraction; only the
// intermediate pyramid (B1, B2) lives in shared memory.
// ---------------------------------------------------------------------------

#define NT      1024
#define N0      32768
#define NROWS   512
#define HALF    16777216   // 512 * 32768, offset of trend in d_out

// Buffer geometry (floats), each with 8-float zeroed front margin
#define B1_ALLOC  (8 + 16388 + 8)          // 16404
#define B2_ALLOC  (8 + 8198 + 10)          // 8216
#define SMEM_FLOATS (B1_ALLOC + B2_ALLOC)  // 24620
#define SMEM_BYTES  (SMEM_FLOATS * 4)      // 98480 bytes -> 2 CTAs/SM

// DEC_LO
#define G0 (-0.010597401784997278f)
#define G1 ( 0.032883011666982945f)
#define G2 ( 0.030841381835986965f)
#define G3 (-0.18703481171888114f)
#define G4 (-0.02798376941698385f)
#define G5 ( 0.6308807679295904f)
#define G6 ( 0.7148465705525415f)
#define G7 ( 0.23037781330885523f)
// H[k] = DEC_LO[7-k]
#define H0 G7
#define H1 G6
#define H2 G5
#define H3 G4
#define H4 G3
#define H5 G2
#define H6 G1
#define H7 G0

__device__ __forceinline__ float dot8(float2 a, float2 b, float2 c, float2 d) {
    float s = a.x * H0;
    s = fmaf(a.y, H1, s);
    s = fmaf(b.x, H2, s);
    s = fmaf(b.y, H3, s);
    s = fmaf(c.x, H4, s);
    s = fmaf(c.y, H5, s);
    s = fmaf(d.x, H6, s);
    s = fmaf(d.y, H7, s);
    return s;
}

// Stage-1 analysis: reads x directly from GLOBAL (guarded at edges).
// out[o] = sum_k x[2o-6+k] * H[k], o in [0, 16387). Pairwise: o = 2m, 2m+1.
__device__ __forceinline__ void afb1(const float* __restrict__ x,
                                     float* __restrict__ out, int tid) {
    const int n_out = 16387;
    const int npair = 8194;
    for (int m = tid; m < npair; m += NT) {
        int base = 4 * m - 6;
        float2 a, b, c, d, e;
        if (m >= 2 && m < 8192) {            // base in [2, 32758]: all in-bounds
            const float2* p = (const float2*)(x + base);
            a = p[0]; b = p[1]; c = p[2]; d = p[3]; e = p[4];
        } else {                              // edges: guarded scalar loads
            float v[10];
#pragma unroll
            for (int k = 0; k < 10; ++k) {
                int ix = base + k;
                v[k] = (ix >= 0 && ix < N0) ? x[ix] : 0.0f;
            }
            a = make_float2(v[0], v[1]); b = make_float2(v[2], v[3]);
            c = make_float2(v[4], v[5]); d = make_float2(v[6], v[7]);
            e = make_float2(v[8], v[9]);
        }
        float s0 = dot8(a, b, c, d);
        float s1 = dot8(b, c, d, e);
        int o = 2 * m;
        if (o + 1 < n_out) *(float2*)(out + o) = make_float2(s0, s1);
        else               out[o] = s0;
    }
    if (tid < 8) out[n_out + tid] = 0.0f;
}

// Analysis from smem: pairwise (outputs 2m, 2m+1 share 5 float2 loads).
__device__ __forceinline__ void afb(const float* __restrict__ in,
                                    float* __restrict__ out,
                                    int n_out, int tid) {
    const int npair = (n_out + 1) >> 1;
    for (int m = tid; m < npair; m += NT) {
        const float2* p = (const float2*)(in + 4 * m - 6);
        float2 a = p[0], b = p[1], c = p[2], d = p[3], e = p[4];
        float s0 = dot8(a, b, c, d);
        float s1 = dot8(b, c, d, e);
        int o = 2 * m;
        if (o + 1 < n_out) *(float2*)(out + o) = make_float2(s0, s1);
        else               out[o] = s0;
    }
    if (tid < 8) out[n_out + tid] = 0.0f;
}

// Synthesis: quad (outputs 4q..4q+3 share 3 float2 loads).
__device__ __forceinline__ void sfb(const float* __restrict__ in,
                                    float* __restrict__ out,
                                    int n_out, int tid) {
    const int nq = (n_out + 3) >> 2;
    for (int q = tid; q < nq; q += NT) {
        const float2* p = (const float2*)(in + 2 * q);
        float2 u = p[0], v = p[1], w = p[2];
        float4 t;
        t.x = fmaf(u.x, G1, fmaf(u.y, G3, fmaf(v.x, G5, v.y * G7)));
        t.y = fmaf(u.x, G0, fmaf(u.y, G2, fmaf(v.x, G4, v.y * G6)));
        t.z = fmaf(u.y, G1, fmaf(v.x, G3, fmaf(v.y, G5, w.x * G7)));
        t.w = fmaf(u.y, G0, fmaf(v.x, G2, fmaf(v.y, G4, w.x * G6)));
        int o = 4 * q;
        if (o + 3 < n_out) *(float4*)(out + o) = t;
        else               *(float2*)(out + o) = make_float2(t.x, t.y);
    }
}

__global__ void __launch_bounds__(NT, 2)
wt_kernel(const float* __restrict__ x, float* __restrict__ out) {
    extern __shared__ float sm[];
    float* B1 = sm + 8;
    float* B2 = sm + B1_ALLOC + 8;

    const int tid = threadIdx.x;
    const int row = blockIdx.x;
    const float* xr = x + (size_t)row * N0;

    // Zero front margins
    if (tid < 8) {
        B1[tid - 8] = 0.0f;
        B2[tid - 8] = 0.0f;
    }
    __syncthreads();

    // Analysis: 32768(global) -> 16387 -> 8197 -> 4102 -> 2054
    afb1(xr, B1, tid);       __syncthreads();
    afb(B1, B2, 8197,  tid); __syncthreads();
    afb(B2, B1, 4102,  tid); __syncthreads();
    afb(B1, B2, 2054,  tid); __syncthreads();

    // Synthesis: 2054 -> 4102 -> 8198 -> 16388 (trims implicit)
    sfb(B2, B1, 4102,  tid); __syncthreads();
    sfb(B1, B2, 8198,  tid); __syncthreads();
    sfb(B2, B1, 16388, tid); __syncthreads();

    // Final upsample 16387 -> 32768 fused with season = x - trend.
    // x re-read from global (coalesced float4).
    float* season = out + (size_t)row * N0;
    float* trend  = out + (size_t)HALF + (size_t)row * N0;
    const float* t3 = B1;
    const float4* x4 = (const float4*)xr;
    float4* s4p = (float4*)season;
    float4* t4p = (float4*)trend;

#pragma unroll 2
    for (int i = 0; i < 8; ++i) {
        int idx = tid + i * NT;          // float4 output index, 0..8191
        int j = idx * 2;                 // t3 base (even -> float2 aligned)
        float2 u = *(const float2*)(t3 + j);
        float2 v = *(const float2*)(t3 + j + 2);
        float  w = t3[j + 4];

        float4 t;
        t.x = fmaf(u.x, G1, fmaf(u.y, G3, fmaf(v.x, G5, v.y * G7)));
        t.y = fmaf(u.x, G0, fmaf(u.y, G2, fmaf(v.x, G4, v.y * G6)));
        t.z = fmaf(u.y, G1, fmaf(v.x, G3, fmaf(v.y, G5, w * G7)));
        t.w = fmaf(u.y, G0, fmaf(v.x, G2, fmaf(v.y, G4, w * G6)));

        float4 xv = x4[idx];
        float4 se = make_float4(xv.x - t.x, xv.y - t.y, xv.z - t.z, xv.w - t.w);
        s4p[idx] = se;
        t4p[idx] = t;
    }
}

extern "C" void kernel_launch(void* const* d_in, const int* in_sizes, int n_in,
                              void* d_out, int out_size) {
    const float* x = (const float*)d_in[0];
    float* out = (float*)d_out;
    cudaFuncSetAttribute(wt_kernel, cudaFuncAttributeMaxDynamicSharedMemorySize,
                         SMEM_BYTES);
    wt_kernel<<<NROWS, NT, SMEM_BYTES>>>(x, out);
}